// round 8
// baseline (speedup 1.0000x reference)
#include <cuda_runtime.h>
#include <cuda_bf16.h>
#include <cstdint>

#define QD        512
#define KD        64
#define NAUX      8
#define B_TOTAL   65536
#define LN_EPS    1e-5f

#define THREADS   256
#define RB        128              // rows per CTA
#define KC        64               // K-chunk
#define NCH       (QD / KC)        // 8 chunks

// smem byte offsets
// A fp32 double buffer: [0,32768) [32768,65536)
// B bf16 hi/lo double:  buf0 hi@65536 lo@74752 ; buf1 hi@83968 lo@93184
#define ABUF_STRIDE 32768
#define B_BASE      65536
#define BBUF_STRIDE 18432
#define BLO_OFF     9216
#define SMEM_BYTES  102400
#define SQM_OFF_F   0              // epilogue: 128x68 f32 (34816 B) aliases A0
#define WVT_OFF_B   65536          // epilogue: 64x68 f32 (17408 B) aliases B0

typedef unsigned long long u64;

__device__ __forceinline__ u64 pack2(float lo, float hi) {
    u64 r; asm("mov.b64 %0, {%1, %2};" : "=l"(r) : "f"(lo), "f"(hi)); return r;
}
__device__ __forceinline__ void unpack2(u64 v, float& lo, float& hi) {
    asm("mov.b64 {%0, %1}, %2;" : "=f"(lo), "=f"(hi) : "l"(v));
}
__device__ __forceinline__ u64 ffma2(u64 a, u64 b, u64 c) {
    u64 d; asm("fma.rn.f32x2 %0, %1, %2, %3;" : "=l"(d) : "l"(a), "l"(b), "l"(c)); return d;
}
__device__ __forceinline__ void cp16(uint32_t dst, const void* src) {
    asm volatile("cp.async.cg.shared.global [%0], [%1], 16;" :: "r"(dst), "l"(src));
}
__device__ __forceinline__ uint32_t cvt_bf2(float hi, float lo) {
    uint32_t r;
    asm("cvt.rn.bf16x2.f32 %0, %1, %2;" : "=r"(r) : "f"(hi), "f"(lo));
    return r;
}
__device__ __forceinline__ void mma_bf16(float* c, uint32_t a0, uint32_t a1,
                                         uint32_t a2, uint32_t a3,
                                         uint32_t b0, uint32_t b1) {
    asm volatile(
        "mma.sync.aligned.m16n8k16.row.col.f32.bf16.bf16.f32 "
        "{%0,%1,%2,%3}, {%4,%5,%6,%7}, {%8,%9}, {%0,%1,%2,%3};"
        : "+f"(c[0]), "+f"(c[1]), "+f"(c[2]), "+f"(c[3])
        : "r"(a0), "r"(a1), "r"(a2), "r"(a3), "r"(b0), "r"(b1));
}
__device__ __forceinline__ void ldsm4(uint32_t& r0, uint32_t& r1, uint32_t& r2,
                                      uint32_t& r3, uint32_t addr) {
    asm volatile("ldmatrix.sync.aligned.m8n8.x4.shared.b16 {%0,%1,%2,%3}, [%4];"
                 : "=r"(r0), "=r"(r1), "=r"(r2), "=r"(r3) : "r"(addr));
}

// B operand: M^T split into bf16 hi/lo.  g_B*[n*QD + k]
__device__ __align__(256) __nv_bfloat16 g_Bhi[KD * QD];
__device__ __align__(256) __nv_bfloat16 g_Blo[KD * QD];

__global__ void lca_compute_M(const float* __restrict__ w_q,
                              const float* __restrict__ w_k) {
    const int j  = threadIdx.x & 63;
    const int il = threadIdx.x >> 6;
    const int i  = blockIdx.x * 4 + il;       // 0..511
    float acc = 0.0f;
#pragma unroll
    for (int e = 0; e < KD; ++e)
        acc = fmaf(w_q[e * QD + i], w_k[e * KD + j], acc);
    __nv_bfloat16 h = __float2bfloat16_rn(acc);
    __nv_bfloat16 l = __float2bfloat16_rn(acc - __bfloat162float(h));
    g_Bhi[j * QD + i] = h;
    g_Blo[j * QD + i] = l;
}

__global__ void __launch_bounds__(THREADS, 2)
lca_main(const float* __restrict__ query,
         const float* __restrict__ kv,
         const float* __restrict__ w_v,
         const float* __restrict__ gamma,
         const float* __restrict__ beta,
         float* __restrict__ out) {
    extern __shared__ float smem[];
    char* smc = (char*)smem;
    const uint32_t su = (uint32_t)__cvta_generic_to_shared(smem);
    const int tid  = threadIdx.x;
    const int wid  = tid >> 5;
    const int lane = tid & 31;
    const int b0   = blockIdx.x * RB;

    float C[8][4];
#pragma unroll
    for (int t = 0; t < 8; ++t)
#pragma unroll
        for (int c = 0; c < 4; ++c) C[t][c] = 0.0f;

    const int rw   = wid * 16;           // warp row base
    const int g    = lane >> 2;          // 0..7
    const int kcol = (lane & 3) * 2;

    // ---- async chunk issue: A fp32 (swizzled f4 groups) + B bf16 hi/lo ----
    auto issue_chunk = [&](int ch) {
        const int i0 = ch * KC;
        const int bi = ch & 1;
        const uint32_t abase = su + bi * ABUF_STRIDE;
        const uint32_t bbase = su + B_BASE + bi * BBUF_STRIDE;
#pragma unroll
        for (int p = 0; p < 8; ++p) {
            int idx = p * THREADS + tid;          // 0..2047
            int r = idx >> 4, c4 = idx & 15;
            uint32_t dst = abase + (uint32_t)(r * 256 + ((c4 ^ (r & 7)) << 4));
            cp16(dst, query + (size_t)(b0 + r) * QD + i0 + c4 * 4);
        }
#pragma unroll
        for (int p = 0; p < 2; ++p) {
            int idx = p * THREADS + tid;          // 0..511
            int n = idx >> 3, k8 = idx & 7;
            cp16(bbase + n * 144 + k8 * 16,
                 (const char*)g_Bhi + (size_t)n * 1024 + i0 * 2 + k8 * 16);
            cp16(bbase + BLO_OFF + n * 144 + k8 * 16,
                 (const char*)g_Blo + (size_t)n * 1024 + i0 * 2 + k8 * 16);
        }
        asm volatile("cp.async.commit_group;");
    };

    issue_chunk(0);

    // A fragment smem addressing (constant across chunks except buffer base)
    const int r0   = rw + g;
    const int aswz = r0 & 7;
    const int ginA = kcol >> 2;           // 0 or 1
    const int aoff_in = (kcol & 3) * 4;   // 0 or 8 bytes

    // ---------------- Mainloop ----------------
#pragma unroll 1
    for (int ch = 0; ch < NCH; ++ch) {
        asm volatile("cp.async.wait_group 0;");
        __syncthreads();    // publishes chunk ch; releases (ch+1)-parity buffers

        if (ch + 1 < NCH) issue_chunk(ch + 1);

        const uint32_t abase = su + (ch & 1) * ABUF_STRIDE;
        const uint32_t bbase = su + B_BASE + (ch & 1) * BBUF_STRIDE;
        const char* a0p = smc + ((ch & 1) * ABUF_STRIDE) + r0 * 256 + aoff_in;
        const char* a1p = a0p + 8 * 256;   // row r0+8, same swizzle (r&7 equal)

#pragma unroll
        for (int kk = 0; kk < 4; ++kk) {
            const int grp0 = (ginA + kk * 4) ^ aswz;
            const int grp2 = (ginA + 2 + kk * 4) ^ aswz;
            float2 q0 = *(const float2*)(a0p + (grp0 << 4));
            float2 q1 = *(const float2*)(a1p + (grp0 << 4));
            float2 q2 = *(const float2*)(a0p + (grp2 << 4));
            float2 q3 = *(const float2*)(a1p + (grp2 << 4));

            uint32_t ah0 = cvt_bf2(q0.y, q0.x);
            uint32_t ah1 = cvt_bf2(q1.y, q1.x);
            uint32_t ah2 = cvt_bf2(q2.y, q2.x);
            uint32_t ah3 = cvt_bf2(q3.y, q3.x);
            uint32_t al0, al1, al2, al3;
            {
                float hx = __uint_as_float(ah0 << 16);
                float hy = __uint_as_float(ah0 & 0xffff0000u);
                al0 = cvt_bf2(q0.y - hy, q0.x - hx);
                hx = __uint_as_float(ah1 << 16);
                hy = __uint_as_float(ah1 & 0xffff0000u);
                al1 = cvt_bf2(q1.y - hy, q1.x - hx);
                hx = __uint_as_float(ah2 << 16);
                hy = __uint_as_float(ah2 & 0xffff0000u);
                al2 = cvt_bf2(q2.y - hy, q2.x - hx);
                hx = __uint_as_float(ah3 << 16);
                hy = __uint_as_float(ah3 & 0xffff0000u);
                al3 = cvt_bf2(q3.y - hy, q3.x - hx);
            }

#pragma unroll
            for (int j = 0; j < 4; ++j) {
                uint32_t nrow  = j * 16 + (lane & 7) + ((lane >> 4) << 3);
                uint32_t khalf = (lane >> 3) & 1;
                uint32_t boff  = nrow * 144 + khalf * 16 + kk * 32;
                uint32_t bh0, bh1, bh2, bh3, bl0, bl1, bl2, bl3;
                ldsm4(bh0, bh1, bh2, bh3, bbase + boff);
                ldsm4(bl0, bl1, bl2, bl3, bbase + BLO_OFF + boff);
                mma_bf16(C[2*j],   ah0, ah1, ah2, ah3, bh0, bh1);
                mma_bf16(C[2*j],   ah0, ah1, ah2, ah3, bl0, bl1);
                mma_bf16(C[2*j],   al0, al1, al2, al3, bh0, bh1);
                mma_bf16(C[2*j+1], ah0, ah1, ah2, ah3, bh2, bh3);
                mma_bf16(C[2*j+1], ah0, ah1, ah2, ah3, bl2, bl3);
                mma_bf16(C[2*j+1], al0, al1, al2, al3, bh2, bh3);
            }
        }
    }
    __syncthreads();   // mainloop smem dead; reuse for sQM / sWvT

    // ---- write qm to smem (pitch 68) ----
    float* sQM = smem + SQM_OFF_F;
#pragma unroll
    for (int t = 0; t < 8; ++t) {
        float* d0 = sQM + (rw + g) * 68     + t * 8 + kcol;
        float* d1 = sQM + (rw + g + 8) * 68 + t * 8 + kcol;
        *(float2*)d0 = make_float2(C[t][0], C[t][1]);
        *(float2*)d1 = make_float2(C[t][2], C[t][3]);
    }
    // fill transposed W_v (aliases dead B0 region)
    float* sWvT = (float*)(smc + WVT_OFF_B);
    for (int idx = tid; idx < KD * KD; idx += THREADS) {
        int e = idx >> 6, d = idx & 63;
        sWvT[d * 68 + e] = w_v[idx];
    }
    __syncthreads();

    // ---------------- Epilogue: attention + W_v + LayerNorm ----------------
    const int sub   = tid & 3;
    const int row32 = tid >> 2;          // 0..63
    float* sS = sQM;                     // row-exact alias

    for (int gg = 0; gg < 2; ++gg) {
        const int r = gg * 64 + row32;
        const size_t b = b0 + r;

        float4 qmv[4];
#pragma unroll
        for (int m = 0; m < 4; ++m)
            qmv[m] = *(const float4*)(sQM + r * 68 + sub * 4 + m * 16);

        const float* kvb = kv + b * (NAUX * KD) + sub * 4;

        float sc[NAUX];
#pragma unroll
        for (int n = 0; n < NAUX; ++n) {
            float p = 0.0f;
#pragma unroll
            for (int m = 0; m < 4; ++m) {
                float4 a = *(const float4*)(kvb + n * KD + m * 16);
                p = fmaf(a.x, qmv[m].x, p);
                p = fmaf(a.y, qmv[m].y, p);
                p = fmaf(a.z, qmv[m].z, p);
                p = fmaf(a.w, qmv[m].w, p);
            }
            sc[n] = p;
        }
#pragma unroll
        for (int n = 0; n < NAUX; ++n) {
            sc[n] += __shfl_xor_sync(0xffffffffu, sc[n], 1);
            sc[n] += __shfl_xor_sync(0xffffffffu, sc[n], 2);
            sc[n] *= 0.125f;
        }
        float mx = sc[0];
#pragma unroll
        for (int n = 1; n < NAUX; ++n) mx = fmaxf(mx, sc[n]);
        float attn[NAUX], ssum = 0.0f;
#pragma unroll
        for (int n = 0; n < NAUX; ++n) { attn[n] = __expf(sc[n] - mx); ssum += attn[n]; }
        float rs = 1.0f / ssum;

        float s16[4][4];
#pragma unroll
        for (int m = 0; m < 4; ++m)
#pragma unroll
            for (int e = 0; e < 4; ++e) s16[m][e] = 0.0f;
#pragma unroll
        for (int n = 0; n < NAUX; ++n) {
            float w = attn[n] * rs;
#pragma unroll
            for (int m = 0; m < 4; ++m) {
                float4 a = *(const float4*)(kvb + n * KD + m * 16);   // L1 hit
                s16[m][0] = fmaf(w, a.x, s16[m][0]);
                s16[m][1] = fmaf(w, a.y, s16[m][1]);
                s16[m][2] = fmaf(w, a.z, s16[m][2]);
                s16[m][3] = fmaf(w, a.w, s16[m][3]);
            }
        }
#pragma unroll
        for (int m = 0; m < 4; ++m)
            *(float4*)(sS + r * 68 + sub * 4 + m * 16) =
                make_float4(s16[m][0], s16[m][1], s16[m][2], s16[m][3]);
    }
    __syncwarp();

    // Stage 4: o = W_v @ s for 2 rows at once
    u64 oacc[2][4][2];
#pragma unroll
    for (int gg = 0; gg < 2; ++gg)
#pragma unroll
        for (int m = 0; m < 4; ++m) { oacc[gg][m][0] = 0ull; oacc[gg][m][1] = 0ull; }

#pragma unroll 4
    for (int d = 0; d < KD; ++d) {
        const float* wr = sWvT + d * 68 + sub * 4;
        u64 w2[4][2];
#pragma unroll
        for (int m = 0; m < 4; ++m) {
            float4 wv = *(const float4*)(wr + m * 16);
            w2[m][0] = pack2(wv.x, wv.y);
            w2[m][1] = pack2(wv.z, wv.w);
        }
#pragma unroll
        for (int gg = 0; gg < 2; ++gg) {
            float sv = sS[(gg * 64 + row32) * 68 + d];
            u64 ss = pack2(sv, sv);
#pragma unroll
            for (int m = 0; m < 4; ++m) {
                oacc[gg][m][0] = ffma2(ss, w2[m][0], oacc[gg][m][0]);
                oacc[gg][m][1] = ffma2(ss, w2[m][1], oacc[gg][m][1]);
            }
        }
    }

    // Stage 5: LayerNorm + output
#pragma unroll
    for (int gg = 0; gg < 2; ++gg) {
        float ov[4][4];
#pragma unroll
        for (int m = 0; m < 4; ++m) {
            unpack2(oacc[gg][m][0], ov[m][0], ov[m][1]);
            unpack2(oacc[gg][m][1], ov[m][2], ov[m][3]);
        }
        float lsum = 0.0f, lsq = 0.0f;
#pragma unroll
        for (int m = 0; m < 4; ++m)
#pragma unroll
            for (int e = 0; e < 4; ++e) {
                lsum += ov[m][e];
                lsq = fmaf(ov[m][e], ov[m][e], lsq);
            }
        lsum += __shfl_xor_sync(0xffffffffu, lsum, 1);
        lsum += __shfl_xor_sync(0xffffffffu, lsum, 2);
        lsq  += __shfl_xor_sync(0xffffffffu, lsq, 1);
        lsq  += __shfl_xor_sync(0xffffffffu, lsq, 2);
        const float mean = lsum * (1.0f / 64.0f);
        const float var  = lsq * (1.0f / 64.0f) - mean * mean;
        const float inv  = rsqrtf(var + LN_EPS);

        const size_t b = b0 + gg * 64 + row32;
        float* op = out + b * KD + sub * 4;
#pragma unroll
        for (int m = 0; m < 4; ++m) {
            float4 gm = *(const float4*)(gamma + sub * 4 + m * 16);
            float4 bt = *(const float4*)(beta  + sub * 4 + m * 16);
            float4 res;
            res.x = fmaf((ov[m][0] - mean) * inv, gm.x, bt.x);
            res.y = fmaf((ov[m][1] - mean) * inv, gm.y, bt.y);
            res.z = fmaf((ov[m][2] - mean) * inv, gm.z, bt.z);
            res.w = fmaf((ov[m][3] - mean) * inv, gm.w, bt.w);
            *(float4*)(op + m * 16) = res;
        }
    }
}

// ---------------- launch ----------------
extern "C" void kernel_launch(void* const* d_in, const int* in_sizes, int n_in,
                              void* d_out, int out_size) {
    const float* query = (const float*)d_in[0];
    const float* kv    = (const float*)d_in[1];
    const float* w_q   = (const float*)d_in[2];
    const float* w_k   = (const float*)d_in[3];
    const float* w_v   = (const float*)d_in[4];
    const float* gamma = (const float*)d_in[5];
    const float* beta  = (const float*)d_in[6];
    float* out = (float*)d_out;

    cudaFuncSetAttribute(lca_main, cudaFuncAttributeMaxDynamicSharedMemorySize, SMEM_BYTES);

    lca_compute_M<<<QD / 4, 256>>>(w_q, w_k);
    lca_main<<<B_TOTAL / RB, THREADS, SMEM_BYTES>>>(query, kv, w_v, gamma, beta, out);
}

// round 9
// speedup vs baseline: 1.6368x; 1.6368x over previous
#include <cuda_runtime.h>
#include <cuda_bf16.h>
#include <cstdint>

#define QD        512
#define KD        64
#define NAUX      8
#define B_TOTAL   65536
#define LN_EPS    1e-5f

#define THREADS   128
#define RB        64               // rows per CTA
#define KC        64               // K-chunk
#define NCH       (QD / KC)        // 8 chunks

// smem byte offsets (single-buffered, 36864 B total)
#define AH_OFF    0                // Ahi: 64 rows x 72 halves = 9216 B
#define AL_OFF    9216             // Alo: 9216 B
#define BH_OFF    18432            // Bhi: 64 x 72 halves = 9216 B
#define BL_OFF    27648            // Blo: 9216 B
#define SMEM_BYTES 36864
#define SQM_OFF_F 0                // epilogue: 64x68 f32 (17408 B) aliases A
#define WVT_OFF_B 18432            // epilogue: 64x68 f32 (17408 B) aliases B

typedef unsigned long long u64;

__device__ __forceinline__ u64 pack2(float lo, float hi) {
    u64 r; asm("mov.b64 %0, {%1, %2};" : "=l"(r) : "f"(lo), "f"(hi)); return r;
}
__device__ __forceinline__ void unpack2(u64 v, float& lo, float& hi) {
    asm("mov.b64 {%0, %1}, %2;" : "=f"(lo), "=f"(hi) : "l"(v));
}
__device__ __forceinline__ u64 ffma2(u64 a, u64 b, u64 c) {
    u64 d; asm("fma.rn.f32x2 %0, %1, %2, %3;" : "=l"(d) : "l"(a), "l"(b), "l"(c)); return d;
}
__device__ __forceinline__ void cp16(uint32_t dst, const void* src) {
    asm volatile("cp.async.cg.shared.global [%0], [%1], 16;" :: "r"(dst), "l"(src));
}
__device__ __forceinline__ uint32_t cvt_bf2(float hi, float lo) {
    uint32_t r;
    asm("cvt.rn.bf16x2.f32 %0, %1, %2;" : "=r"(r) : "f"(hi), "f"(lo));
    return r;
}
__device__ __forceinline__ void mma_bf16(float* c, uint32_t a0, uint32_t a1,
                                         uint32_t a2, uint32_t a3,
                                         uint32_t b0, uint32_t b1) {
    asm volatile(
        "mma.sync.aligned.m16n8k16.row.col.f32.bf16.bf16.f32 "
        "{%0,%1,%2,%3}, {%4,%5,%6,%7}, {%8,%9}, {%0,%1,%2,%3};"
        : "+f"(c[0]), "+f"(c[1]), "+f"(c[2]), "+f"(c[3])
        : "r"(a0), "r"(a1), "r"(a2), "r"(a3), "r"(b0), "r"(b1));
}
__device__ __forceinline__ void ldsm4(uint32_t& r0, uint32_t& r1, uint32_t& r2,
                                      uint32_t& r3, uint32_t addr) {
    asm volatile("ldmatrix.sync.aligned.m8n8.x4.shared.b16 {%0,%1,%2,%3}, [%4];"
                 : "=r"(r0), "=r"(r1), "=r"(r2), "=r"(r3) : "r"(addr));
}

// B operand: M^T split into bf16 hi/lo.  g_B*[n*QD + k]
__device__ __align__(256) __nv_bfloat16 g_Bhi[KD * QD];
__device__ __align__(256) __nv_bfloat16 g_Blo[KD * QD];

__global__ void lca_compute_M(const float* __restrict__ w_q,
                              const float* __restrict__ w_k) {
    const int j  = threadIdx.x & 63;
    const int il = threadIdx.x >> 6;
    const int i  = blockIdx.x * 4 + il;       // 0..511
    float acc = 0.0f;
#pragma unroll
    for (int e = 0; e < KD; ++e)
        acc = fmaf(w_q[e * QD + i], w_k[e * KD + j], acc);
    __nv_bfloat16 h = __float2bfloat16_rn(acc);
    __nv_bfloat16 l = __float2bfloat16_rn(acc - __bfloat162float(h));
    g_Bhi[j * QD + i] = h;
    g_Blo[j * QD + i] = l;
}

__global__ void __launch_bounds__(THREADS, 4)
lca_main(const float* __restrict__ query,
         const float* __restrict__ kv,
         const float* __restrict__ w_v,
         const float* __restrict__ gamma,
         const float* __restrict__ beta,
         float* __restrict__ out) {
    extern __shared__ float smem[];
    char* smc = (char*)smem;
    const uint32_t su = (uint32_t)__cvta_generic_to_shared(smem);
    const int tid  = threadIdx.x;
    const int wid  = tid >> 5;           // 0..3
    const int lane = tid & 31;
    const int b0   = blockIdx.x * RB;

    float C[8][4];
#pragma unroll
    for (int t = 0; t < 8; ++t)
#pragma unroll
        for (int c = 0; c < 4; ++c) C[t][c] = 0.0f;

    const int rw   = wid * 16;           // warp row base (0..48)
    const int g    = lane >> 2;          // 0..7
    const int kcol = (lane & 3) * 2;

    // ---------------- Mainloop: qm = query @ M (HMMA bf16-split) ----------------
    for (int ch = 0; ch < NCH; ++ch) {
        const int i0 = ch * KC;
        __syncthreads();   // previous chunk's reads complete (4-warp barrier)

        // B chunk via cp.async: hi/lo, [n][k] pitch 72 halves (144 B)
#pragma unroll
        for (int p = 0; p < 4; ++p) {
            int idx = p * THREADS + tid;          // 0..511
            int n = idx >> 3, k8 = idx & 7;
            cp16(su + BH_OFF + n * 144 + k8 * 16,
                 (const char*)g_Bhi + (size_t)n * 1024 + i0 * 2 + k8 * 16);
            cp16(su + BL_OFF + n * 144 + k8 * 16,
                 (const char*)g_Blo + (size_t)n * 1024 + i0 * 2 + k8 * 16);
        }
        asm volatile("cp.async.commit_group;");

        // A chunk: LDG fp32 -> bf16 hi/lo -> STS, pitch 72 halves
        {
            float4 v[8];
#pragma unroll
            for (int p = 0; p < 8; ++p) {
                int idx = p * THREADS + tid;      // 0..1023
                int r = idx >> 4, c4 = idx & 15;
                v[p] = *(const float4*)(query + (size_t)(b0 + r) * QD + i0 + c4 * 4);
            }
#pragma unroll
            for (int p = 0; p < 8; ++p) {
                int idx = p * THREADS + tid;
                int r = idx >> 4, c4 = idx & 15;
                uint32_t h01 = cvt_bf2(v[p].y, v[p].x);
                uint32_t h23 = cvt_bf2(v[p].w, v[p].z);
                float hx = __uint_as_float(h01 << 16);
                float hy = __uint_as_float(h01 & 0xffff0000u);
                float hz = __uint_as_float(h23 << 16);
                float hw = __uint_as_float(h23 & 0xffff0000u);
                uint32_t l01 = cvt_bf2(v[p].y - hy, v[p].x - hx);
                uint32_t l23 = cvt_bf2(v[p].w - hw, v[p].z - hz);
                *(uint2*)(smc + AH_OFF + r * 144 + c4 * 8) = make_uint2(h01, h23);
                *(uint2*)(smc + AL_OFF + r * 144 + c4 * 8) = make_uint2(l01, l23);
            }
        }
        asm volatile("cp.async.wait_group 0;");
        __syncthreads();

        // compute: 4 k16 steps
#pragma unroll
        for (int kk = 0; kk < 4; ++kk) {
            const int k0 = kk * 16;
            uint32_t ah0 = *(const uint32_t*)(smc + AH_OFF + (rw + g)     * 144 + (k0 + kcol) * 2);
            uint32_t ah1 = *(const uint32_t*)(smc + AH_OFF + (rw + g + 8) * 144 + (k0 + kcol) * 2);
            uint32_t ah2 = *(const uint32_t*)(smc + AH_OFF + (rw + g)     * 144 + (k0 + kcol + 8) * 2);
            uint32_t ah3 = *(const uint32_t*)(smc + AH_OFF + (rw + g + 8) * 144 + (k0 + kcol + 8) * 2);
            uint32_t al0 = *(const uint32_t*)(smc + AL_OFF + (rw + g)     * 144 + (k0 + kcol) * 2);
            uint32_t al1 = *(const uint32_t*)(smc + AL_OFF + (rw + g + 8) * 144 + (k0 + kcol) * 2);
            uint32_t al2 = *(const uint32_t*)(smc + AL_OFF + (rw + g)     * 144 + (k0 + kcol + 8) * 2);
            uint32_t al3 = *(const uint32_t*)(smc + AL_OFF + (rw + g + 8) * 144 + (k0 + kcol + 8) * 2);

#pragma unroll
            for (int j = 0; j < 4; ++j) {
                uint32_t nrow  = j * 16 + (lane & 7) + ((lane >> 4) << 3);
                uint32_t khalf = (lane >> 3) & 1;
                uint32_t boff  = nrow * 144 + khalf * 16 + k0 * 2;
                uint32_t bh0, bh1, bh2, bh3, bl0, bl1, bl2, bl3;
                ldsm4(bh0, bh1, bh2, bh3, su + BH_OFF + boff);
                ldsm4(bl0, bl1, bl2, bl3, su + BL_OFF + boff);
                mma_bf16(C[2*j],   ah0, ah1, ah2, ah3, bh0, bh1);
                mma_bf16(C[2*j],   ah0, ah1, ah2, ah3, bl0, bl1);
                mma_bf16(C[2*j],   al0, al1, al2, al3, bh0, bh1);
                mma_bf16(C[2*j+1], ah0, ah1, ah2, ah3, bh2, bh3);
                mma_bf16(C[2*j+1], ah0, ah1, ah2, ah3, bl2, bl3);
                mma_bf16(C[2*j+1], al0, al1, al2, al3, bh2, bh3);
            }
        }
    }
    __syncthreads();   // mainloop smem dead; reuse for sQM / sWvT

    // ---- write qm to smem (pitch 68, aliases A region) ----
    float* sQM = smem + SQM_OFF_F;
#pragma unroll
    for (int t = 0; t < 8; ++t) {
        float* d0 = sQM + (rw + g) * 68     + t * 8 + kcol;
        float* d1 = sQM + (rw + g + 8) * 68 + t * 8 + kcol;
        *(float2*)d0 = make_float2(C[t][0], C[t][1]);
        *(float2*)d1 = make_float2(C[t][2], C[t][3]);
    }
    // transposed W_v (aliases dead B region)
    float* sWvT = (float*)(smc + WVT_OFF_B);
    for (int idx = tid; idx < KD * KD; idx += THREADS) {
        int e = idx >> 6, d = idx & 63;
        sWvT[d * 68 + e] = w_v[idx];
    }
    __syncthreads();

    // ---------------- Epilogue: attention + W_v + LayerNorm ----------------
    const int sub   = tid & 3;
    const int row32 = tid >> 2;          // 0..31
    float* sS = sQM;                     // row-exact alias

    for (int gg = 0; gg < 2; ++gg) {
        const int r = gg * 32 + row32;
        const size_t b = b0 + r;

        float4 qmv[4];
#pragma unroll
        for (int m = 0; m < 4; ++m)
            qmv[m] = *(const float4*)(sQM + r * 68 + sub * 4 + m * 16);

        const float* kvb = kv + b * (NAUX * KD) + sub * 4;

        float sc[NAUX];
#pragma unroll
        for (int n = 0; n < NAUX; ++n) {
            float p = 0.0f;
#pragma unroll
            for (int m = 0; m < 4; ++m) {
                float4 a = *(const float4*)(kvb + n * KD + m * 16);
                p = fmaf(a.x, qmv[m].x, p);
                p = fmaf(a.y, qmv[m].y, p);
                p = fmaf(a.z, qmv[m].z, p);
                p = fmaf(a.w, qmv[m].w, p);
            }
            sc[n] = p;
        }
#pragma unroll
        for (int n = 0; n < NAUX; ++n) {
            sc[n] += __shfl_xor_sync(0xffffffffu, sc[n], 1);
            sc[n] += __shfl_xor_sync(0xffffffffu, sc[n], 2);
            sc[n] *= 0.125f;
        }
        float mx = sc[0];
#pragma unroll
        for (int n = 1; n < NAUX; ++n) mx = fmaxf(mx, sc[n]);
        float attn[NAUX], ssum = 0.0f;
#pragma unroll
        for (int n = 0; n < NAUX; ++n) { attn[n] = __expf(sc[n] - mx); ssum += attn[n]; }
        float rs = 1.0f / ssum;

        float s16[4][4];
#pragma unroll
        for (int m = 0; m < 4; ++m)
#pragma unroll
            for (int e = 0; e < 4; ++e) s16[m][e] = 0.0f;
#pragma unroll
        for (int n = 0; n < NAUX; ++n) {
            float w = attn[n] * rs;
#pragma unroll
            for (int m = 0; m < 4; ++m) {
                float4 a = *(const float4*)(kvb + n * KD + m * 16);   // L1 hit
                s16[m][0] = fmaf(w, a.x, s16[m][0]);
                s16[m][1] = fmaf(w, a.y, s16[m][1]);
                s16[m][2] = fmaf(w, a.z, s16[m][2]);
                s16[m][3] = fmaf(w, a.w, s16[m][3]);
            }
        }
#pragma unroll
        for (int m = 0; m < 4; ++m)
            *(float4*)(sS + r * 68 + sub * 4 + m * 16) =
                make_float4(s16[m][0], s16[m][1], s16[m][2], s16[m][3]);
    }
    __syncwarp();

    // Stage 4: o = W_v @ s for 2 rows at once
    u64 oacc[2][4][2];
#pragma unroll
    for (int gg = 0; gg < 2; ++gg)
#pragma unroll
        for (int m = 0; m < 4; ++m) { oacc[gg][m][0] = 0ull; oacc[gg][m][1] = 0ull; }

#pragma unroll 4
    for (int d = 0; d < KD; ++d) {
        const float* wr = sWvT + d * 68 + sub * 4;
        u64 w2[4][2];
#pragma unroll
        for (int m = 0; m < 4; ++m) {
            float4 wv = *(const float4*)(wr + m * 16);
            w2[m][0] = pack2(wv.x, wv.y);
            w2[m][1] = pack2(wv.z, wv.w);
        }
#pragma unroll
        for (int gg = 0; gg < 2; ++gg) {
            float sv = sS[(gg * 32 + row32) * 68 + d];
            u64 ss = pack2(sv, sv);
#pragma unroll
            for (int m = 0; m < 4; ++m) {
                oacc[gg][m][0] = ffma2(ss, w2[m][0], oacc[gg][m][0]);
                oacc[gg][m][1] = ffma2(ss, w2[m][1], oacc[gg][m][1]);
            }
        }
    }

    // Stage 5: LayerNorm + output
#pragma unroll
    for (int gg = 0; gg < 2; ++gg) {
        float ov[4][4];
#pragma unroll
        for (int m = 0; m < 4; ++m) {
            unpack2(oacc[gg][m][0], ov[m][0], ov[m][1]);
            unpack2(oacc[gg][m][1], ov[m][2], ov[m][3]);
        }
        float lsum = 0.0f, lsq = 0.0f;
#pragma unroll
        for (int m = 0; m < 4; ++m)
#pragma unroll
            for (int e = 0; e < 4; ++e) {
                lsum += ov[m][e];
                lsq = fmaf(ov[m][e], ov[m][e], lsq);
            }
        lsum += __shfl_xor_sync(0xffffffffu, lsum, 1);
        lsum += __shfl_xor_sync(0xffffffffu, lsum, 2);
        lsq  += __shfl_xor_sync(0xffffffffu, lsq, 1);
        lsq  += __shfl_xor_sync(0xffffffffu, lsq, 2);
        const float mean = lsum * (1.0f / 64.0f);
        const float var  = lsq * (1.0f / 64.0f) - mean * mean;
        const float inv  = rsqrtf(var + LN_EPS);

        const size_t b = b0 + gg * 32 + row32;
        float* op = out + b * KD + sub * 4;
#pragma unroll
        for (int m = 0; m < 4; ++m) {
            float4 gm = *(const float4*)(gamma + sub * 4 + m * 16);
            float4 bt = *(const float4*)(beta  + sub * 4 + m * 16);
            float4 res;
            res.x = fmaf((ov[m][0] - mean) * inv, gm.x, bt.x);
            res.y = fmaf((ov[m][1] - mean) * inv, gm.y, bt.y);
            res.z = fmaf((ov[m][2] - mean) * inv, gm.z, bt.z);
            res.w = fmaf((ov[m][3] - mean) * inv, gm.w, bt.w);
            *(float4*)(op + m * 16) = res;
        }
    }
}

// ---------------- launch ----------------
extern "C" void kernel_launch(void* const* d_in, const int* in_sizes, int n_in,
                              void* d_out, int out_size) {
    const float* query = (const float*)d_in[0];
    const float* kv    = (const float*)d_in[1];
    const float* w_q   = (const float*)d_in[2];
    const float* w_k   = (const float*)d_in[3];
    const float* w_v   = (const float*)d_in[4];
    const float* gamma = (const float*)d_in[5];
    const float* beta  = (const float*)d_in[6];
    float* out = (float*)d_out;

    cudaFuncSetAttribute(lca_main, cudaFuncAttributeMaxDynamicSharedMemorySize, SMEM_BYTES);

    lca_compute_M<<<QD / 4, 256>>>(w_q, w_k);
    lca_main<<<B_TOTAL / RB, THREADS, SMEM_BYTES>>>(query, kv, w_v, gamma, beta, out);
}